// round 8
// baseline (speedup 1.0000x reference)
#include <cuda_runtime.h>
#include <cuda_fp16.h>
#include <cstdint>

#define GRID_H 1024
#define GRID_W 1024
#define DIM_FEAT 32
#define HW (GRID_H * GRID_W)
#define NBINS 64
#define CHUNK 2048
#define NMAX 2100000

// 64 MB table: params transposed to [H, W, C] fp16.
__device__ __half g_params_t[(size_t)DIM_FEAT * HW];
// Binning state (reset every replay by zero_kernel).
__device__ int g_hist[NBINS];
__device__ int g_base[NBINS];
__device__ int g_perm[NMAX];

__device__ __forceinline__ int bin_of(float y) {
    const float iy = (y + 1.0f) * 0.5f * (float)(GRID_H - 1);
    int by = (int)floorf(iy);
    by = min(max(by, 0), GRID_H - 1);
    return by >> 4;   // 64 bins of 16 rows
}

__global__ void zero_kernel() {
    if (threadIdx.x < NBINS) g_hist[threadIdx.x] = 0;
}

__global__ void hist_kernel(const float2* __restrict__ coord, int n) {
    __shared__ int s_cnt[NBINS];
    if (threadIdx.x < NBINS) s_cnt[threadIdx.x] = 0;
    __syncthreads();
    for (int p = blockIdx.x * blockDim.x + threadIdx.x; p < n;
         p += gridDim.x * blockDim.x) {
        atomicAdd(&s_cnt[bin_of(__ldg(&coord[p]).y)], 1);
    }
    __syncthreads();
    if (threadIdx.x < NBINS) atomicAdd(&g_hist[threadIdx.x], s_cnt[threadIdx.x]);
}

__global__ void scan_kernel() {
    if (threadIdx.x == 0) {
        int acc = 0;
        for (int b = 0; b < NBINS; b++) {
            g_base[b] = acc;
            acc += g_hist[b];
        }
    }
}

__global__ void scatter_kernel(const float2* __restrict__ coord, int n) {
    __shared__ int s_cnt[NBINS];
    __shared__ int s_start[NBINS];
    const int tid = threadIdx.x;
    const int p0 = blockIdx.x * CHUNK;
    if (tid < NBINS) s_cnt[tid] = 0;
    __syncthreads();
#pragma unroll
    for (int k = 0; k < CHUNK / 256; k++) {
        const int p = p0 + k * 256 + tid;
        if (p < n) atomicAdd(&s_cnt[bin_of(__ldg(&coord[p]).y)], 1);
    }
    __syncthreads();
    if (tid < NBINS) {
        s_start[tid] = atomicAdd(&g_base[tid], s_cnt[tid]);
        s_cnt[tid] = 0;
    }
    __syncthreads();
#pragma unroll
    for (int k = 0; k < CHUNK / 256; k++) {
        const int p = p0 + k * 256 + tid;
        if (p < n) {
            const int b = bin_of(__ldg(&coord[p]).y);
            const int r = atomicAdd(&s_cnt[b], 1);
            g_perm[s_start[b] + r] = p;
        }
    }
}

// ---------------------------------------------------------------------------
// Transpose [C, H*W] fp32 -> [H*W, C] fp16; table stored with evict-last.
// ---------------------------------------------------------------------------
__global__ void transpose_kernel(const float* __restrict__ p,
                                 __half* __restrict__ pt) {
    __shared__ float tile[32][33];
    const int pix0 = blockIdx.x * 32;
    const int tx = threadIdx.x;
    const int ty = threadIdx.y;
    const int l = ty * 32 + tx;

    uint64_t pol;
    asm volatile("createpolicy.fractional.L2::evict_last.b64 %0, 1.0;"
                 : "=l"(pol));

#pragma unroll
    for (int i = 0; i < 32; i += 8) {
        tile[ty + i][tx] = __ldcs(&p[(size_t)(ty + i) * HW + pix0 + tx]);
    }
    __syncthreads();

    unsigned* ptv = (unsigned*)pt;
#pragma unroll
    for (int it = 0; it < 2; it++) {
        const int pix = it * 16 + (l >> 4);
        const int c2 = l & 15;
        const __half2 h = __floats2half2_rn(tile[2 * c2 + 0][pix],
                                            tile[2 * c2 + 1][pix]);
        const unsigned hv = *(const unsigned*)&h;
        unsigned* dst = ptv + (size_t)(pix0 + pix) * (DIM_FEAT / 2) + c2;
        asm volatile("st.global.L2::cache_hint.u32 [%0], %1, %2;"
                     :: "l"(dst), "r"(hv), "l"(pol));
    }
}

__device__ __forceinline__ uint4 ldg_el(const __half* p, uint64_t pol) {
    uint4 r;
    asm volatile("ld.global.nc.L2::cache_hint.v4.u32 {%0,%1,%2,%3}, [%4], %5;"
                 : "=r"(r.x), "=r"(r.y), "=r"(r.z), "=r"(r.w)
                 : "l"(p), "l"(pol));
    return r;
}

// ---------------------------------------------------------------------------
// Bilinear sample in bin order: 4 lanes per point, lane = 8 channels.
// Consecutive perm entries hit the same ~1MB table region -> L2-hot gathers.
// ---------------------------------------------------------------------------
__global__ void sample_kernel(const float2* __restrict__ coord,
                              const __half* __restrict__ pt,
                              float* __restrict__ out, int n) {
    const int t = blockIdx.x * blockDim.x + threadIdx.x;
    const int i = t >> 2;        // position in permutation
    const int q = t & 3;         // channel octet
    if (i >= n) return;
    const int pidx = __ldg(&g_perm[i]);

    uint64_t pol;
    asm volatile("createpolicy.fractional.L2::evict_last.b64 %0, 1.0;"
                 : "=l"(pol));

    const float2 xy = __ldg(&coord[pidx]);

    const float ix = (xy.x + 1.0f) * 0.5f * (float)(GRID_W - 1);
    const float iy = (xy.y + 1.0f) * 0.5f * (float)(GRID_H - 1);

    const float ix0f = floorf(ix);
    const float iy0f = floorf(iy);
    const float fx = ix - ix0f;
    const float fy = iy - iy0f;

    const float w_nw = (1.0f - fx) * (1.0f - fy);
    const float w_ne = fx * (1.0f - fy);
    const float w_sw = (1.0f - fx) * fy;
    const float w_se = fx * fy;

    int ix0 = min(max((int)ix0f, 0), GRID_W - 1);
    int iy0 = min(max((int)iy0f, 0), GRID_H - 1);
    const int ix1 = min(ix0 + 1, GRID_W - 1);
    const int iy1 = min(iy0 + 1, GRID_H - 1);

    const size_t row0 = (size_t)iy0 * GRID_W;
    const size_t row1 = (size_t)iy1 * GRID_W;
    const int cq = 8 * q;
    const uint4 r_nw = ldg_el(pt + (row0 + ix0) * DIM_FEAT + cq, pol);
    const uint4 r_ne = ldg_el(pt + (row0 + ix1) * DIM_FEAT + cq, pol);
    const uint4 r_sw = ldg_el(pt + (row1 + ix0) * DIM_FEAT + cq, pol);
    const uint4 r_se = ldg_el(pt + (row1 + ix1) * DIM_FEAT + cq, pol);

    float acc[8];
#pragma unroll
    for (int j = 0; j < 8; j++) acc[j] = 0.0f;

    auto accum = [&](const uint4& r, float w) {
        const unsigned u[4] = {r.x, r.y, r.z, r.w};
#pragma unroll
        for (int j = 0; j < 4; j++) {
            const float2 v = __half22float2(*(const __half2*)&u[j]);
            acc[2 * j + 0] = fmaf(v.x, w, acc[2 * j + 0]);
            acc[2 * j + 1] = fmaf(v.y, w, acc[2 * j + 1]);
        }
    };
    accum(r_nw, w_nw);
    accum(r_ne, w_ne);
    accum(r_sw, w_sw);
    accum(r_se, w_se);

    float4* o = (float4*)(out + (size_t)pidx * DIM_FEAT + cq);
    __stcs(o + 0, make_float4(acc[0], acc[1], acc[2], acc[3]));
    __stcs(o + 1, make_float4(acc[4], acc[5], acc[6], acc[7]));
}

extern "C" void kernel_launch(void* const* d_in, const int* in_sizes, int n_in,
                              void* d_out, int out_size) {
    const float2* coord = (const float2*)d_in[0];  // [N, 2]
    const float* params = (const float*)d_in[1];   // [1, 32, 1024, 1024]
    float* out = (float*)d_out;                    // [N, 32]
    const int n = in_sizes[0] / 2;

    __half* pt;
    cudaGetSymbolAddress((void**)&pt, g_params_t);

    // Binning prepass: hist -> scan -> scatter (deterministic output overall).
    zero_kernel<<<1, 64>>>();
    hist_kernel<<<512, 256>>>(coord, n);
    scan_kernel<<<1, 32>>>();
    scatter_kernel<<<(n + CHUNK - 1) / CHUNK, 256>>>(coord, n);

    // Transpose params into L2-resident fp16 table.
    dim3 tb(32, 8);
    transpose_kernel<<<HW / 32, tb>>>(params, pt);

    // Sample in bin order.
    const int threads = 256;
    const long long total = (long long)n * 4;
    sample_kernel<<<(int)((total + threads - 1) / threads), threads>>>(
        coord, pt, out, n);
}

// round 9
// speedup vs baseline: 1.1353x; 1.1353x over previous
#include <cuda_runtime.h>
#include <cuda_fp16.h>
#include <cstdint>

#define GRID_H 1024
#define GRID_W 1024
#define DIM_FEAT 32
#define HW (GRID_H * GRID_W)

// 64 MB table: params transposed to [H, W, C] fp16.
__device__ __half g_params_t[(size_t)DIM_FEAT * HW];

// ---------------------------------------------------------------------------
// Transpose [C, H*W] fp32 -> [H*W, C] fp16. Params read evict-first,
// table written evict-last (R7 config: fastest measured transpose).
// ---------------------------------------------------------------------------
__global__ void transpose_kernel(const float* __restrict__ p,
                                 __half* __restrict__ pt) {
    __shared__ float tile[32][33];
    const int pix0 = blockIdx.x * 32;
    const int tx = threadIdx.x;
    const int ty = threadIdx.y;
    const int l = ty * 32 + tx;

    uint64_t pol;
    asm volatile("createpolicy.fractional.L2::evict_last.b64 %0, 1.0;"
                 : "=l"(pol));

#pragma unroll
    for (int i = 0; i < 32; i += 8) {
        tile[ty + i][tx] = __ldcs(&p[(size_t)(ty + i) * HW + pix0 + tx]);
    }
    __syncthreads();

    unsigned* ptv = (unsigned*)pt;
#pragma unroll
    for (int it = 0; it < 2; it++) {
        const int pix = it * 16 + (l >> 4);
        const int c2 = l & 15;
        const __half2 h = __floats2half2_rn(tile[2 * c2 + 0][pix],
                                            tile[2 * c2 + 1][pix]);
        const unsigned hv = *(const unsigned*)&h;
        unsigned* dst = ptv + (size_t)(pix0 + pix) * (DIM_FEAT / 2) + c2;
        asm volatile("st.global.L2::cache_hint.u32 [%0], %1, %2;"
                     :: "l"(dst), "r"(hv), "l"(pol));
    }
}

// 256-bit gather (sm_100+): 8 x b32 = 16 fp16 channels in one instruction.
__device__ __forceinline__ void ldg_v8(const __half* p, unsigned r[8]) {
    asm volatile(
        "ld.global.nc.v8.b32 {%0,%1,%2,%3,%4,%5,%6,%7}, [%8];"
        : "=r"(r[0]), "=r"(r[1]), "=r"(r[2]), "=r"(r[3]),
          "=r"(r[4]), "=r"(r[5]), "=r"(r[6]), "=r"(r[7])
        : "l"(p));
}

// ---------------------------------------------------------------------------
// Bilinear sample: 2 lanes per point, each lane = 16 channels (32B).
// 4 x 32B v8 gathers per lane (corner = 64B over 2 lanes, coalesced).
// Plain gathers (hints measured neutral-to-harmful), streaming out stores.
// ---------------------------------------------------------------------------
__global__ void sample_kernel(const float2* __restrict__ coord,
                              const __half* __restrict__ pt,
                              float* __restrict__ out, int n) {
    const int t = blockIdx.x * blockDim.x + threadIdx.x;
    const int pidx = t >> 1;     // point index
    const int lane = t & 1;      // channel half (16 channels)
    if (pidx >= n) return;

    const float2 xy = __ldcs(&coord[pidx]);

    // align_corners=True mapping
    const float ix = (xy.x + 1.0f) * 0.5f * (float)(GRID_W - 1);
    const float iy = (xy.y + 1.0f) * 0.5f * (float)(GRID_H - 1);

    const float ix0f = floorf(ix);
    const float iy0f = floorf(iy);
    const float fx = ix - ix0f;
    const float fy = iy - iy0f;

    const float w_nw = (1.0f - fx) * (1.0f - fy);
    const float w_ne = fx * (1.0f - fy);
    const float w_sw = (1.0f - fx) * fy;
    const float w_se = fx * fy;

    int ix0 = min(max((int)ix0f, 0), GRID_W - 1);
    int iy0 = min(max((int)iy0f, 0), GRID_H - 1);
    const int ix1 = min(ix0 + 1, GRID_W - 1);
    const int iy1 = min(iy0 + 1, GRID_H - 1);

    const size_t row0 = (size_t)iy0 * GRID_W;
    const size_t row1 = (size_t)iy1 * GRID_W;
    const int cb = 16 * lane;    // channel base for this lane

    unsigned r_nw[8], r_ne[8], r_sw[8], r_se[8];
    ldg_v8(pt + (row0 + ix0) * DIM_FEAT + cb, r_nw);
    ldg_v8(pt + (row0 + ix1) * DIM_FEAT + cb, r_ne);
    ldg_v8(pt + (row1 + ix0) * DIM_FEAT + cb, r_sw);
    ldg_v8(pt + (row1 + ix1) * DIM_FEAT + cb, r_se);

    float acc[16];
#pragma unroll
    for (int i = 0; i < 16; i++) acc[i] = 0.0f;

    auto accum = [&](const unsigned* u, float w) {
#pragma unroll
        for (int j = 0; j < 8; j++) {
            const float2 v = __half22float2(*(const __half2*)&u[j]);
            acc[2 * j + 0] = fmaf(v.x, w, acc[2 * j + 0]);
            acc[2 * j + 1] = fmaf(v.y, w, acc[2 * j + 1]);
        }
    };
    accum(r_nw, w_nw);
    accum(r_ne, w_ne);
    accum(r_sw, w_sw);
    accum(r_se, w_se);

    float4* o = (float4*)(out + (size_t)pidx * DIM_FEAT + cb);
    __stcs(o + 0, make_float4(acc[0], acc[1], acc[2], acc[3]));
    __stcs(o + 1, make_float4(acc[4], acc[5], acc[6], acc[7]));
    __stcs(o + 2, make_float4(acc[8], acc[9], acc[10], acc[11]));
    __stcs(o + 3, make_float4(acc[12], acc[13], acc[14], acc[15]));
}

extern "C" void kernel_launch(void* const* d_in, const int* in_sizes, int n_in,
                              void* d_out, int out_size) {
    const float2* coord = (const float2*)d_in[0];  // [N, 2]
    const float* params = (const float*)d_in[1];   // [1, 32, 1024, 1024]
    float* out = (float*)d_out;                    // [N, 32]
    const int n = in_sizes[0] / 2;

    __half* pt;
    cudaGetSymbolAddress((void**)&pt, g_params_t);

    dim3 tb(32, 8);
    transpose_kernel<<<HW / 32, tb>>>(params, pt);

    const int threads = 256;
    const long long total = (long long)n * 2;
    sample_kernel<<<(int)((total + threads - 1) / threads), threads>>>(
        coord, pt, out, n);
}

// round 11
// speedup vs baseline: 1.2558x; 1.1062x over previous
#include <cuda_runtime.h>
#include <cuda_fp16.h>
#include <cstdint>

#define GRID_H 1024
#define GRID_W 1024
#define DIM_FEAT 32
#define HW (GRID_H * GRID_W)

// 64 MB table: params transposed to [H, W, C] fp16.
__device__ __half g_params_t[(size_t)DIM_FEAT * HW];

// ---------------------------------------------------------------------------
// Transpose [C, H*W] fp32 -> [H*W, C] fp16. Params read evict-first (stream),
// table written evict-last so it's L2-resident for the sample kernel.
// (R7 config: fastest measured transpose, 30.3us incl. launch overheads.)
// ---------------------------------------------------------------------------
__global__ void transpose_kernel(const float* __restrict__ p,
                                 __half* __restrict__ pt) {
    __shared__ float tile[32][33];
    const int pix0 = blockIdx.x * 32;
    const int tx = threadIdx.x;
    const int ty = threadIdx.y;
    const int l = ty * 32 + tx;

    uint64_t pol;
    asm volatile("createpolicy.fractional.L2::evict_last.b64 %0, 1.0;"
                 : "=l"(pol));

#pragma unroll
    for (int i = 0; i < 32; i += 8) {
        tile[ty + i][tx] = __ldcs(&p[(size_t)(ty + i) * HW + pix0 + tx]);
    }
    __syncthreads();

    unsigned* ptv = (unsigned*)pt;
#pragma unroll
    for (int it = 0; it < 2; it++) {
        const int pix = it * 16 + (l >> 4);
        const int c2 = l & 15;
        const __half2 h = __floats2half2_rn(tile[2 * c2 + 0][pix],
                                            tile[2 * c2 + 1][pix]);
        const unsigned hv = *(const unsigned*)&h;
        unsigned* dst = ptv + (size_t)(pix0 + pix) * (DIM_FEAT / 2) + c2;
        asm volatile("st.global.L2::cache_hint.u32 [%0], %1, %2;"
                     :: "l"(dst), "r"(hv), "l"(pol));
    }
}

// ---------------------------------------------------------------------------
// Bilinear sample (R2 config: fastest measured, 87.3us).
// 4 lanes per point, each lane = 8 channels: 4 x 16B uint4 gathers
// (64B coalesced per corner across lanes); streaming float4 out stores.
// ---------------------------------------------------------------------------
__global__ void sample_kernel(const float2* __restrict__ coord,
                              const __half* __restrict__ pt,
                              float* __restrict__ out, int n) {
    const int t = blockIdx.x * blockDim.x + threadIdx.x;
    const int pidx = t >> 2;     // point index
    const int q = t & 3;         // channel octet (8 channels)
    if (pidx >= n) return;

    const float2 xy = __ldcs(&coord[pidx]);

    // align_corners=True mapping
    const float ix = (xy.x + 1.0f) * 0.5f * (float)(GRID_W - 1);
    const float iy = (xy.y + 1.0f) * 0.5f * (float)(GRID_H - 1);

    const float ix0f = floorf(ix);
    const float iy0f = floorf(iy);
    const float fx = ix - ix0f;
    const float fy = iy - iy0f;

    const float w_nw = (1.0f - fx) * (1.0f - fy);
    const float w_ne = fx * (1.0f - fy);
    const float w_sw = (1.0f - fx) * fy;
    const float w_se = fx * fy;

    int ix0 = min(max((int)ix0f, 0), GRID_W - 1);
    int iy0 = min(max((int)iy0f, 0), GRID_H - 1);
    const int ix1 = min(ix0 + 1, GRID_W - 1);
    const int iy1 = min(iy0 + 1, GRID_H - 1);

    const size_t row0 = (size_t)iy0 * GRID_W;
    const size_t row1 = (size_t)iy1 * GRID_W;
    const int cq = 8 * q;
    const uint4 r_nw = *(const uint4*)(pt + (row0 + ix0) * DIM_FEAT + cq);
    const uint4 r_ne = *(const uint4*)(pt + (row0 + ix1) * DIM_FEAT + cq);
    const uint4 r_sw = *(const uint4*)(pt + (row1 + ix0) * DIM_FEAT + cq);
    const uint4 r_se = *(const uint4*)(pt + (row1 + ix1) * DIM_FEAT + cq);

    float acc[8];
#pragma unroll
    for (int i = 0; i < 8; i++) acc[i] = 0.0f;

    auto accum = [&](const uint4& r, float w) {
        const unsigned u[4] = {r.x, r.y, r.z, r.w};
#pragma unroll
        for (int j = 0; j < 4; j++) {
            const float2 v = __half22float2(*(const __half2*)&u[j]);
            acc[2 * j + 0] = fmaf(v.x, w, acc[2 * j + 0]);
            acc[2 * j + 1] = fmaf(v.y, w, acc[2 * j + 1]);
        }
    };
    accum(r_nw, w_nw);
    accum(r_ne, w_ne);
    accum(r_sw, w_sw);
    accum(r_se, w_se);

    float4* o = (float4*)(out + (size_t)pidx * DIM_FEAT + cq);
    __stcs(o + 0, make_float4(acc[0], acc[1], acc[2], acc[3]));
    __stcs(o + 1, make_float4(acc[4], acc[5], acc[6], acc[7]));
}

extern "C" void kernel_launch(void* const* d_in, const int* in_sizes, int n_in,
                              void* d_out, int out_size) {
    const float2* coord = (const float2*)d_in[0];  // [N, 2]
    const float* params = (const float*)d_in[1];   // [1, 32, 1024, 1024]
    float* out = (float*)d_out;                    // [N, 32]
    const int n = in_sizes[0] / 2;

    __half* pt;
    cudaGetSymbolAddress((void**)&pt, g_params_t);

    dim3 tb(32, 8);
    transpose_kernel<<<HW / 32, tb>>>(params, pt);

    const int threads = 256;
    const long long total = (long long)n * 4;
    sample_kernel<<<(int)((total + threads - 1) / threads), threads>>>(
        coord, pt, out, n);
}

// round 12
// speedup vs baseline: 1.3657x; 1.0875x over previous
#include <cuda_runtime.h>
#include <cuda_fp16.h>
#include <cstdint>

#define GRID_H 1024
#define GRID_W 1024
#define DIM_FEAT 32
#define HW (GRID_H * GRID_W)

// 64 MB table: params transposed to [H, W, C] fp16.
__device__ __half g_params_t[(size_t)DIM_FEAT * HW];

// ---------------------------------------------------------------------------
// Transpose [C, H*W] fp32 -> [H*W, C] fp16. Params read evict-first (stream),
// table written with evict-last hint (best measured non-sample config).
// ---------------------------------------------------------------------------
__global__ void transpose_kernel(const float* __restrict__ p,
                                 __half* __restrict__ pt) {
    __shared__ float tile[32][33];
    const int pix0 = blockIdx.x * 32;
    const int tx = threadIdx.x;
    const int ty = threadIdx.y;
    const int l = ty * 32 + tx;

    uint64_t pol;
    asm volatile("createpolicy.fractional.L2::evict_last.b64 %0, 1.0;"
                 : "=l"(pol));

#pragma unroll
    for (int i = 0; i < 32; i += 8) {
        tile[ty + i][tx] = __ldcs(&p[(size_t)(ty + i) * HW + pix0 + tx]);
    }
    __syncthreads();

    unsigned* ptv = (unsigned*)pt;
#pragma unroll
    for (int it = 0; it < 2; it++) {
        const int pix = it * 16 + (l >> 4);
        const int c2 = l & 15;
        const __half2 h = __floats2half2_rn(tile[2 * c2 + 0][pix],
                                            tile[2 * c2 + 1][pix]);
        const unsigned hv = *(const unsigned*)&h;
        unsigned* dst = ptv + (size_t)(pix0 + pix) * (DIM_FEAT / 2) + c2;
        asm volatile("st.global.L2::cache_hint.u32 [%0], %1, %2;"
                     :: "l"(dst), "r"(hv), "l"(pol));
    }
}

// 256-bit streaming store: one instruction per lane's 8 fp32 channels.
__device__ __forceinline__ void stcs_v8(float* p, const float a[8]) {
    asm volatile(
        "st.global.cs.v8.b32 [%0], {%1,%2,%3,%4,%5,%6,%7,%8};"
        :: "l"(p),
           "f"(a[0]), "f"(a[1]), "f"(a[2]), "f"(a[3]),
           "f"(a[4]), "f"(a[5]), "f"(a[6]), "f"(a[7])
        : "memory");
}

// ---------------------------------------------------------------------------
// Bilinear sample: 4 lanes per point, each lane = 8 channels.
// 4 x 16B uint4 gathers (64B coalesced per corner across lanes);
// single 32B v8 streaming store per lane (halves store wavefronts).
// ---------------------------------------------------------------------------
__global__ void sample_kernel(const float2* __restrict__ coord,
                              const __half* __restrict__ pt,
                              float* __restrict__ out, int n) {
    const int t = blockIdx.x * blockDim.x + threadIdx.x;
    const int pidx = t >> 2;     // point index
    const int q = t & 3;         // channel octet (8 channels)
    if (pidx >= n) return;

    const float2 xy = __ldcs(&coord[pidx]);

    // align_corners=True mapping
    const float ix = (xy.x + 1.0f) * 0.5f * (float)(GRID_W - 1);
    const float iy = (xy.y + 1.0f) * 0.5f * (float)(GRID_H - 1);

    const float ix0f = floorf(ix);
    const float iy0f = floorf(iy);
    const float fx = ix - ix0f;
    const float fy = iy - iy0f;

    const float w_nw = (1.0f - fx) * (1.0f - fy);
    const float w_ne = fx * (1.0f - fy);
    const float w_sw = (1.0f - fx) * fy;
    const float w_se = fx * fy;

    int ix0 = min(max((int)ix0f, 0), GRID_W - 1);
    int iy0 = min(max((int)iy0f, 0), GRID_H - 1);
    const int ix1 = min(ix0 + 1, GRID_W - 1);
    const int iy1 = min(iy0 + 1, GRID_H - 1);

    const size_t row0 = (size_t)iy0 * GRID_W;
    const size_t row1 = (size_t)iy1 * GRID_W;
    const int cq = 8 * q;
    const uint4 r_nw = *(const uint4*)(pt + (row0 + ix0) * DIM_FEAT + cq);
    const uint4 r_ne = *(const uint4*)(pt + (row0 + ix1) * DIM_FEAT + cq);
    const uint4 r_sw = *(const uint4*)(pt + (row1 + ix0) * DIM_FEAT + cq);
    const uint4 r_se = *(const uint4*)(pt + (row1 + ix1) * DIM_FEAT + cq);

    float acc[8];
#pragma unroll
    for (int i = 0; i < 8; i++) acc[i] = 0.0f;

    auto accum = [&](const uint4& r, float w) {
        const unsigned u[4] = {r.x, r.y, r.z, r.w};
#pragma unroll
        for (int j = 0; j < 4; j++) {
            const float2 v = __half22float2(*(const __half2*)&u[j]);
            acc[2 * j + 0] = fmaf(v.x, w, acc[2 * j + 0]);
            acc[2 * j + 1] = fmaf(v.y, w, acc[2 * j + 1]);
        }
    };
    accum(r_nw, w_nw);
    accum(r_ne, w_ne);
    accum(r_sw, w_sw);
    accum(r_se, w_se);

    stcs_v8(out + (size_t)pidx * DIM_FEAT + cq, acc);
}

extern "C" void kernel_launch(void* const* d_in, const int* in_sizes, int n_in,
                              void* d_out, int out_size) {
    const float2* coord = (const float2*)d_in[0];  // [N, 2]
    const float* params = (const float*)d_in[1];   // [1, 32, 1024, 1024]
    float* out = (float*)d_out;                    // [N, 32]
    const int n = in_sizes[0] / 2;

    __half* pt;
    cudaGetSymbolAddress((void**)&pt, g_params_t);

    dim3 tb(32, 8);
    transpose_kernel<<<HW / 32, tb>>>(params, pt);

    const int threads = 256;
    const long long total = (long long)n * 4;
    sample_kernel<<<(int)((total + threads - 1) / threads), threads>>>(
        coord, pt, out, n);
}